// round 14
// baseline (speedup 1.0000x reference)
#include <cuda_runtime.h>
#include <cuda_bf16.h>
#include <cuda_fp16.h>
#include <math.h>
#include <stdint.h>

#define NPTS 262144
#define HID 128
#define NSTEPS 50
#define AS_LD 129
#define ROWS 128
#define LDAW 68   // uint32 words per tile row (136 halves)

#define OUT_US    ((size_t)(NSTEPS + 1) * NPTS * 2)
#define OUT_TIMES (OUT_US + (size_t)NSTEPS * NPTS * 2)

__device__ float g_dctx[NPTS * HID];
__device__ float g_cctx[NPTS * HID];
__device__ float g_tvd[NSTEPS * HID];
__device__ float g_tvc[NSTEPS * HID];
__device__ float g_dt[NSTEPS];
__device__ float g_gs[NSTEPS];

// fast silu (fp32): 1 MUFU + 2 FMA
__device__ __forceinline__ float siluf(float x) {
    float t;
    asm("tanh.approx.f32 %0, %1;" : "=f"(t) : "f"(x * 0.5f));
    return x * fmaf(0.5f, t, 0.5f);
}

__device__ __forceinline__ uint32_t smem_u32(const void* p) {
    uint32_t a;
    asm("{ .reg .u64 t; cvta.to.shared.u64 t, %1; cvt.u32.u64 %0, t; }" : "=r"(a) : "l"(p));
    return a;
}

#define MMAH(d, a, b0, b1) asm volatile( \
    "mma.sync.aligned.m16n8k16.row.col.f32.f16.f16.f32 " \
    "{%0,%1,%2,%3},{%4,%5,%6,%7},{%8,%9},{%0,%1,%2,%3};" \
    : "+f"((d)[0]), "+f"((d)[1]), "+f"((d)[2]), "+f"((d)[3]) \
    : "r"((a)[0]), "r"((a)[1]), "r"((a)[2]), "r"((a)[3]), "r"(b0), "r"(b1))

#define LDSM4(r, addr) asm volatile( \
    "ldmatrix.sync.aligned.m8n8.x4.shared.b16 {%0,%1,%2,%3}, [%4];" \
    : "=r"((r)[0]), "=r"((r)[1]), "=r"((r)[2]), "=r"((r)[3]) : "r"(addr))

// ---------- FFMA2 GEMM (ctx precompute, known-good) ----------
__device__ __forceinline__ void gemm_core(const float* __restrict__ As,
                                          const float* __restrict__ Ws,
                                          int r0, int c0, unsigned long long (&acc)[4][4]) {
#pragma unroll
    for (int i = 0; i < 4; ++i)
#pragma unroll
        for (int j = 0; j < 4; ++j) acc[i][j] = 0ull;
#pragma unroll 4
    for (int k = 0; k < HID; ++k) {
        unsigned long long h[4];
#pragma unroll
        for (int i = 0; i < 4; ++i) {
            unsigned v = __float_as_uint(As[(r0 + i) * AS_LD + k]);
            asm("mov.b64 %0, {%1, %1};" : "=l"(h[i]) : "r"(v));
        }
        const float* wr = Ws + k * HID + c0;
        ulonglong2 wa = *(const ulonglong2*)(wr);
        ulonglong2 wb = *(const ulonglong2*)(wr + 4);
#pragma unroll
        for (int i = 0; i < 4; ++i) {
            asm("fma.rn.f32x2 %0, %1, %2, %0;" : "+l"(acc[i][0]) : "l"(h[i]), "l"(wa.x));
            asm("fma.rn.f32x2 %0, %1, %2, %0;" : "+l"(acc[i][1]) : "l"(h[i]), "l"(wa.y));
            asm("fma.rn.f32x2 %0, %1, %2, %0;" : "+l"(acc[i][2]) : "l"(h[i]), "l"(wb.x));
            asm("fma.rn.f32x2 %0, %1, %2, %0;" : "+l"(acc[i][3]) : "l"(h[i]), "l"(wb.y));
        }
    }
}

// both ctx GEMMs in one launch: which = blockIdx.x >> 12
__global__ void __launch_bounds__(256, 2)
ctx_kernel(const float* __restrict__ Xp, const float* __restrict__ Xc,
           const float* __restrict__ dW1, const float* __restrict__ db1,
           const float* __restrict__ cW1, const float* __restrict__ cb1) {
    extern __shared__ float sm[];
    float* Ws = sm;
    float* Xs = sm + HID * HID;
    int which = blockIdx.x >> 12;
    const float* X  = which ? Xc : Xp;
    const float* W1 = which ? cW1 : dW1;
    const float* b1 = which ? cb1 : db1;
    float* out = which ? g_cctx : g_dctx;
    int tid = threadIdx.x;
    size_t row0 = (size_t)(blockIdx.x & 4095) * 64;
    for (int i = tid; i < HID * HID; i += 256) Ws[i] = W1[2 * HID + i];
#pragma unroll 4
    for (int i = tid; i < 64 * HID; i += 256) {
        int r = i >> 7, c = i & 127;
        Xs[r * AS_LD + c] = X[(row0 + r) * HID + c];
    }
    __syncthreads();
    int r0 = (tid >> 4) * 4, c0 = (tid & 15) * 8;
    unsigned long long acc[4][4];
    gemm_core(Xs, Ws, r0, c0, acc);
#pragma unroll
    for (int i = 0; i < 4; ++i) {
        size_t base = (row0 + r0 + i) * HID + c0;
#pragma unroll
        for (int j = 0; j < 4; ++j) {
            unsigned lo, hi;
            asm("mov.b64 {%0, %1}, %2;" : "=r"(lo), "=r"(hi) : "l"(acc[i][j]));
            float2 v;
            v.x = __uint_as_float(lo) + b1[c0 + 2 * j];
            v.y = __uint_as_float(hi) + b1[c0 + 2 * j + 1];
            *(float2*)&out[base + 2 * j] = v;
        }
    }
}

__global__ void __launch_bounds__(128)
step_const_kernel(const float* __restrict__ times, const float* __restrict__ freqs,
                  const float* __restrict__ dW1, const float* __restrict__ cW1,
                  const float* __restrict__ logd, float* __restrict__ out) {
    int s = blockIdx.x, t = threadIdx.x;
    __shared__ float temb[32];
    float t_i = times[s];
    if (t < 32) {
        float a = 6.28318530717958647692f * t_i * freqs[t & 15];
        temb[t] = (t < 16) ? sinf(a) : cosf(a);
    }
    __syncthreads();
    float sd = 0.0f, sc = 0.0f;
#pragma unroll
    for (int k = 0; k < 32; ++k) {
        sd += temb[k] * dW1[(130 + k) * HID + t];
        sc += temb[k] * cW1[(130 + k) * HID + t];
    }
    g_tvd[s * HID + t] = sd;
    g_tvc[s * HID + t] = sc;
    if (t == 0) {
        float dt = times[s + 1] - t_i;
        g_dt[s] = dt;
        g_gs[s] = log1pf(expf(logd[0])) * (1.0f - t_i) * sqrtf(fmaxf(dt, 1e-12f));
    }
    if (s == 0 && t < NSTEPS + 1) out[OUT_TIMES + t] = times[t];
}

// ---------- main HMMA SDE kernel: 1024 threads, net-parallel halves ----------
#define T_AD  0
#define T_AC  8704
#define T_WDH 17408
#define T_WCH 26112
#define T_FLT 34816
#define SDE_WORDS (T_FLT + 2052)
#define SDE_SMEM (SDE_WORDS * 4)

// GEMM + fused epilogue for one net; 16 warps, warp tile 16 rows x 64 cols
__device__ __forceinline__ void net_pass(uint32_t At_b, uint32_t W_b,
                                         const float* __restrict__ b2,
                                         const float* __restrict__ w3,
                                         float* __restrict__ st0, float* __restrict__ st1,
                                         int widh, int lane) {
    int wm = widh & 7, wn = widh >> 3, g = lane >> 2, tg = lane & 3;
    float acc[8][4];
#pragma unroll
    for (int nt = 0; nt < 8; ++nt)
#pragma unroll
        for (int q = 0; q < 4; ++q) acc[nt][q] = 0.0f;

    int jj = lane >> 3;
    // A frag addr: matrix j -> row_off = (j&1)*8 + (lane&7), k_off halves = (j>>1)*8
    uint32_t aAddr = At_b + (uint32_t)(wm * 16 + (jj & 1) * 8 + (lane & 7)) * 272u
                   + (uint32_t)(jj >> 1) * 16u;
    // B frag addr: matrix j -> n_off = (j>>1)*8 + (lane&7), k_off halves = (j&1)*8
    uint32_t bAddr = W_b + (uint32_t)(wn * 64 + (jj >> 1) * 8 + (lane & 7)) * 272u
                   + (uint32_t)(jj & 1) * 16u;

#pragma unroll
    for (int kc = 0; kc < 8; ++kc) {
        uint32_t a[4];
        LDSM4(a, aAddr + kc * 32u);
#pragma unroll
        for (int ntt = 0; ntt < 4; ++ntt) {
            uint32_t b[4];
            LDSM4(b, bAddr + kc * 32u + (uint32_t)ntt * 4352u);
            MMAH(acc[2 * ntt],     a, b[0], b[1]);
            MMAH(acc[2 * ntt + 1], a, b[2], b[3]);
        }
    }

    // epilogue: bias + silu(fp32) + partial layer3 dot (warp covers 64 cols, 16 rows)
    float p0[2] = {0, 0}, p1[2] = {0, 0};
#pragma unroll
    for (int nt = 0; nt < 8; ++nt) {
        int c0 = wn * 64 + nt * 8 + tg * 2;
        float bA = b2[c0], bB = b2[c0 + 1];
        float2 wA = *(const float2*)(w3 + c0 * 2);
        float2 wB = *(const float2*)(w3 + c0 * 2 + 2);
#pragma unroll
        for (int hf = 0; hf < 2; ++hf) {   // hf=0: row g, hf=1: row g+8
            float h0 = siluf(acc[nt][hf * 2] + bA);
            float h1 = siluf(acc[nt][hf * 2 + 1] + bB);
            p0[hf] += h0 * wA.x + h1 * wB.x;
            p1[hf] += h0 * wA.y + h1 * wB.y;
        }
    }
#pragma unroll
    for (int i = 0; i < 2; ++i) {
        p0[i] += __shfl_xor_sync(~0u, p0[i], 1);
        p0[i] += __shfl_xor_sync(~0u, p0[i], 2);
        p1[i] += __shfl_xor_sync(~0u, p1[i], 1);
        p1[i] += __shfl_xor_sync(~0u, p1[i], 2);
    }
    if (tg == 0) {
        float* st = wn ? st1 : st0;
#pragma unroll
        for (int i = 0; i < 2; ++i) {
            int row = wm * 16 + g + i * 8;
            st[row * 2]     = p0[i];
            st[row * 2 + 1] = p1[i];
        }
    }
}

__global__ void __launch_bounds__(1024, 1)
sde_mma_kernel(const float* __restrict__ z0, const float* __restrict__ noise,
               const float* __restrict__ dW1, const float* __restrict__ dW2,
               const float* __restrict__ db2, const float* __restrict__ dW3,
               const float* __restrict__ db3,
               const float* __restrict__ cW1, const float* __restrict__ cW2,
               const float* __restrict__ cb2, const float* __restrict__ cW3,
               const float* __restrict__ cb3, float* __restrict__ out) {
    extern __shared__ uint32_t sw[];
    float* fs   = (float*)(sw + T_FLT);
    float* zsm  = fs;            // 256
    float* b2d  = fs + 256;      // 128
    float* b2c  = fs + 384;      // 128
    float* w3d  = fs + 512;      // 256
    float* w3c  = fs + 768;      // 256
    float* su0  = fs + 1024;     // 256
    float* su1  = fs + 1280;     // 256
    float* sf0  = fs + 1536;     // 256
    float* sf1  = fs + 1792;     // 256
    float* b3s  = fs + 2048;     // 4

    int tid = threadIdx.x, lane = tid & 31;
    int h = tid >> 9;            // half: 0=diffusion, 1=cnf
    int htid = tid & 511;
    int widh = htid >> 5;        // warp within half (0..15)
    size_t row0 = (size_t)blockIdx.x * ROWS;
    uint32_t sb = smem_u32(sw);

    // W2 transposed (Wt[n][k]) single fp16, both nets
    for (int i = tid; i < HID * HID; i += 1024) {
        int k = i >> 7, n = i & 127;
        ((__half*)(sw + T_WDH))[n * 136 + k] = __float2half(dW2[i]);
        ((__half*)(sw + T_WCH))[n * 136 + k] = __float2half(cW2[i]);
    }
    if (tid < 128)      b2d[tid] = db2[tid];
    else if (tid < 256) b2c[tid - 128] = cb2[tid - 128];
    else if (tid < 512) { int j = tid - 256; w3d[j] = dW3[j]; }
    else if (tid < 768) { int j = tid - 512; w3c[j] = cW3[j]; }
    if (tid < 2)   { b3s[tid] = db3[tid]; b3s[2 + tid] = cb3[tid]; }
    if (tid < 256) {
        float zv = z0[row0 * 2 + tid];
        zsm[tid] = zv;
        out[row0 * 2 + tid] = zv;   // traj[0]
    }

    // per-thread layer1 constants (column fixed per thread)
    int cc = (htid & 63) * 2;
    int r0l = htid >> 6;             // 0..7, stride 8 -> 16 rows each
    const float* W1g = h ? cW1 : dW1;
    float w1aa = W1g[cc], w1ab = W1g[cc + 1];
    float w1ba = W1g[HID + cc], w1bb = W1g[HID + cc + 1];
    const float* prebase = (h ? g_cctx : g_dctx) + row0 * HID + cc;
    const float* tvg = h ? g_tvc : g_tvd;
    uint32_t* At = sw + (h ? T_AC : T_AD);
    uint32_t At_b = sb + (h ? T_AC : T_AD) * 4u;
    uint32_t W_b  = sb + (h ? T_WCH : T_WDH) * 4u;
    const float* b2 = h ? b2c : b2d;
    const float* w3 = h ? w3c : w3d;
    float* st0 = h ? sf0 : su0;
    float* st1 = h ? sf1 : su1;
    int aw = (cc >> 1);
    const uint32_t HALFC = 0x38003800u;   // (0.5, 0.5) f16x2
    __syncthreads();

    for (int s = 0; s < NSTEPS; ++s) {
        float2 tvv = *(const float2*)(tvg + s * HID + cc);
        float dt = g_dt[s], gsc = g_gs[s];
        float xi = 0.0f;
        if (tid < 256) xi = noise[(size_t)s * ((size_t)NPTS * 2) + row0 * 2 + tid];

        // layer1 (f16x2 tanh silu) -> fp16 A tile
        {
            int r = r0l;
#pragma unroll 4
            for (int k = 0; k < 16; ++k, r += 8) {
                float2 pv = *(const float2*)(prebase + r * HID);
                float za = zsm[2 * r], zb = zsm[2 * r + 1];
                float x0 = pv.x + tvv.x + za * w1aa + zb * w1ba;
                float x1 = pv.y + tvv.y + za * w1ab + zb * w1bb;
                uint32_t xp, xh, t, u, hp;
                asm("cvt.rn.f16x2.f32 %0,%1,%2;" : "=r"(xp) : "f"(x1), "f"(x0));
                asm("mul.rn.f16x2 %0,%1,%2;" : "=r"(xh) : "r"(xp), "r"(HALFC));
                asm("tanh.approx.f16x2 %0,%1;" : "=r"(t) : "r"(xh));
                asm("fma.rn.f16x2 %0,%1,%2,%3;" : "=r"(u) : "r"(t), "r"(HALFC), "r"(HALFC));
                asm("mul.rn.f16x2 %0,%1,%2;" : "=r"(hp) : "r"(xp), "r"(u));
                At[r * LDAW + aw] = hp;
            }
        }
        asm volatile("bar.sync %0, 512;" :: "r"(1 + h) : "memory");

        net_pass(At_b, W_b, b2, w3, st0, st1, widh, lane);
        __syncthreads();

        if (tid < 256) {   // SDE update: 256 threads = 128 rows x 2 dims
            float au = su0[tid] + su1[tid] + b3s[tid & 1];
            float af = sf0[tid] + sf1[tid] + b3s[2 + (tid & 1)];
            size_t gi = row0 * 2 + tid;
            float zn = zsm[tid] + (af + au) * dt + xi * gsc;
            out[OUT_US + (size_t)s * ((size_t)NPTS * 2) + gi] = au;
            out[(size_t)(s + 1) * ((size_t)NPTS * 2) + gi]    = zn;
            zsm[tid] = zn;
        }
        __syncthreads();   // zsm visible, stages free for next step
    }
}

extern "C" void kernel_launch(void* const* d_in, const int* in_sizes, int n_in,
                              void* d_out, int out_size) {
    (void)in_sizes; (void)n_in; (void)out_size;
    const float* z0    = (const float*)d_in[0];
    const float* pctx  = (const float*)d_in[1];
    const float* cctx  = (const float*)d_in[2];
    const float* times = (const float*)d_in[3];
    const float* noise = (const float*)d_in[4];
    const float* freqs = (const float*)d_in[5];
    const float* dW1   = (const float*)d_in[6];
    const float* db1   = (const float*)d_in[7];
    const float* dW2   = (const float*)d_in[8];
    const float* db2   = (const float*)d_in[9];
    const float* dW3   = (const float*)d_in[10];
    const float* db3   = (const float*)d_in[11];
    const float* cW1   = (const float*)d_in[12];
    const float* cb1   = (const float*)d_in[13];
    const float* cW2   = (const float*)d_in[14];
    const float* cb2   = (const float*)d_in[15];
    const float* cW3   = (const float*)d_in[16];
    const float* cb3   = (const float*)d_in[17];
    const float* logd  = (const float*)d_in[18];
    float* out = (float*)d_out;

    const int CTX_SMEM = (HID * HID + 64 * AS_LD) * (int)sizeof(float);
    static int done = 0;
    if (!done) {
        cudaFuncSetAttribute(ctx_kernel, cudaFuncAttributeMaxDynamicSharedMemorySize, CTX_SMEM);
        cudaFuncSetAttribute(sde_mma_kernel, cudaFuncAttributeMaxDynamicSharedMemorySize, SDE_SMEM);
        done = 1;
    }
    step_const_kernel<<<NSTEPS, 128>>>(times, freqs, dW1, cW1, logd, out);
    ctx_kernel<<<2 * (NPTS / 64), 256, CTX_SMEM>>>(pctx, cctx, dW1, db1, cW1, cb1);
    sde_mma_kernel<<<NPTS / ROWS, 1024, SDE_SMEM>>>(z0, noise, dW1, dW2, db2, dW3, db3,
                                                    cW1, cW2, cb2, cW3, cb3, out);
}

// round 15
// speedup vs baseline: 1.7284x; 1.7284x over previous
#include <cuda_runtime.h>
#include <cuda_bf16.h>
#include <cuda_fp16.h>
#include <math.h>
#include <stdint.h>

#define NPTS 262144
#define HID 128
#define NSTEPS 50
#define AS_LD 129
#define ROWS 128
#define LDAW 68   // uint32 words per tile row (136 halves)

#define OUT_US    ((size_t)(NSTEPS + 1) * NPTS * 2)
#define OUT_TIMES (OUT_US + (size_t)NSTEPS * NPTS * 2)

__device__ float g_dctx[NPTS * HID];
__device__ float g_cctx[NPTS * HID];
__device__ float g_tvd[NSTEPS * HID];
__device__ float g_tvc[NSTEPS * HID];
__device__ float g_dt[NSTEPS];
__device__ float g_gs[NSTEPS];

// fast silu (fp32): 1 MUFU + 2 FMA
__device__ __forceinline__ float siluf(float x) {
    float t;
    asm("tanh.approx.f32 %0, %1;" : "=f"(t) : "f"(x * 0.5f));
    return x * fmaf(0.5f, t, 0.5f);
}

__device__ __forceinline__ uint32_t smem_u32(const void* p) {
    uint32_t a;
    asm("{ .reg .u64 t; cvta.to.shared.u64 t, %1; cvt.u32.u64 %0, t; }" : "=r"(a) : "l"(p));
    return a;
}

#define MMAH(d, a0, a1, a2, a3, b0, b1) asm volatile( \
    "mma.sync.aligned.m16n8k16.row.col.f32.f16.f16.f32 " \
    "{%0,%1,%2,%3},{%4,%5,%6,%7},{%8,%9},{%0,%1,%2,%3};" \
    : "+f"((d)[0]), "+f"((d)[1]), "+f"((d)[2]), "+f"((d)[3]) \
    : "r"(a0), "r"(a1), "r"(a2), "r"(a3), "r"(b0), "r"(b1))

#define LDSM4(r, addr) asm volatile( \
    "ldmatrix.sync.aligned.m8n8.x4.shared.b16 {%0,%1,%2,%3}, [%4];" \
    : "=r"((r)[0]), "=r"((r)[1]), "=r"((r)[2]), "=r"((r)[3]) : "r"(addr))

// ---------- FFMA2 GEMM (ctx precompute, known-good) ----------
__device__ __forceinline__ void gemm_core(const float* __restrict__ As,
                                          const float* __restrict__ Ws,
                                          int r0, int c0, unsigned long long (&acc)[4][4]) {
#pragma unroll
    for (int i = 0; i < 4; ++i)
#pragma unroll
        for (int j = 0; j < 4; ++j) acc[i][j] = 0ull;
#pragma unroll 4
    for (int k = 0; k < HID; ++k) {
        unsigned long long h[4];
#pragma unroll
        for (int i = 0; i < 4; ++i) {
            unsigned v = __float_as_uint(As[(r0 + i) * AS_LD + k]);
            asm("mov.b64 %0, {%1, %1};" : "=l"(h[i]) : "r"(v));
        }
        const float* wr = Ws + k * HID + c0;
        ulonglong2 wa = *(const ulonglong2*)(wr);
        ulonglong2 wb = *(const ulonglong2*)(wr + 4);
#pragma unroll
        for (int i = 0; i < 4; ++i) {
            asm("fma.rn.f32x2 %0, %1, %2, %0;" : "+l"(acc[i][0]) : "l"(h[i]), "l"(wa.x));
            asm("fma.rn.f32x2 %0, %1, %2, %0;" : "+l"(acc[i][1]) : "l"(h[i]), "l"(wa.y));
            asm("fma.rn.f32x2 %0, %1, %2, %0;" : "+l"(acc[i][2]) : "l"(h[i]), "l"(wb.x));
            asm("fma.rn.f32x2 %0, %1, %2, %0;" : "+l"(acc[i][3]) : "l"(h[i]), "l"(wb.y));
        }
    }
}

// both ctx GEMMs in one launch: which = blockIdx.x >> 12
__global__ void __launch_bounds__(256, 2)
ctx_kernel(const float* __restrict__ Xp, const float* __restrict__ Xc,
           const float* __restrict__ dW1, const float* __restrict__ db1,
           const float* __restrict__ cW1, const float* __restrict__ cb1) {
    extern __shared__ float sm[];
    float* Ws = sm;
    float* Xs = sm + HID * HID;
    int which = blockIdx.x >> 12;
    const float* X  = which ? Xc : Xp;
    const float* W1 = which ? cW1 : dW1;
    const float* b1 = which ? cb1 : db1;
    float* out = which ? g_cctx : g_dctx;
    int tid = threadIdx.x;
    size_t row0 = (size_t)(blockIdx.x & 4095) * 64;
    for (int i = tid; i < HID * HID; i += 256) Ws[i] = W1[2 * HID + i];
#pragma unroll 4
    for (int i = tid; i < 64 * HID; i += 256) {
        int r = i >> 7, c = i & 127;
        Xs[r * AS_LD + c] = X[(row0 + r) * HID + c];
    }
    __syncthreads();
    int r0 = (tid >> 4) * 4, c0 = (tid & 15) * 8;
    unsigned long long acc[4][4];
    gemm_core(Xs, Ws, r0, c0, acc);
#pragma unroll
    for (int i = 0; i < 4; ++i) {
        size_t base = (row0 + r0 + i) * HID + c0;
#pragma unroll
        for (int j = 0; j < 4; ++j) {
            unsigned lo, hi;
            asm("mov.b64 {%0, %1}, %2;" : "=r"(lo), "=r"(hi) : "l"(acc[i][j]));
            float2 v;
            v.x = __uint_as_float(lo) + b1[c0 + 2 * j];
            v.y = __uint_as_float(hi) + b1[c0 + 2 * j + 1];
            *(float2*)&out[base + 2 * j] = v;
        }
    }
}

__global__ void __launch_bounds__(128)
step_const_kernel(const float* __restrict__ times, const float* __restrict__ freqs,
                  const float* __restrict__ dW1, const float* __restrict__ cW1,
                  const float* __restrict__ logd, float* __restrict__ out) {
    int s = blockIdx.x, t = threadIdx.x;
    __shared__ float temb[32];
    float t_i = times[s];
    if (t < 32) {
        float a = 6.28318530717958647692f * t_i * freqs[t & 15];
        temb[t] = (t < 16) ? sinf(a) : cosf(a);
    }
    __syncthreads();
    float sd = 0.0f, sc = 0.0f;
#pragma unroll
    for (int k = 0; k < 32; ++k) {
        sd += temb[k] * dW1[(130 + k) * HID + t];
        sc += temb[k] * cW1[(130 + k) * HID + t];
    }
    g_tvd[s * HID + t] = sd;
    g_tvc[s * HID + t] = sc;
    if (t == 0) {
        float dt = times[s + 1] - t_i;
        g_dt[s] = dt;
        g_gs[s] = log1pf(expf(logd[0])) * (1.0f - t_i) * sqrtf(fmaxf(dt, 1e-12f));
    }
    if (s == 0 && t < NSTEPS + 1) out[OUT_TIMES + t] = times[t];
}

// ---------- main HMMA SDE kernel: 512 threads, net-parallel halves ----------
#define T_AD  0
#define T_AC  8704
#define T_WDH 17408
#define T_WCH 26112
#define T_FLT 34816
#define SDE_WORDS (T_FLT + 2052)
#define SDE_SMEM (SDE_WORDS * 4)

// GEMM + fused epilogue for one net; 8 warps (widh 0..7), warp tile 32r x 64c
__device__ __forceinline__ void net_pass(uint32_t At_b, uint32_t W_b,
                                         const float* __restrict__ b2,
                                         const float* __restrict__ w3,
                                         float* __restrict__ st0, float* __restrict__ st1,
                                         int widh, int lane) {
    int wm = widh & 3, wn = widh >> 2, g = lane >> 2, tg = lane & 3;
    float acc[2][8][4];
#pragma unroll
    for (int mt = 0; mt < 2; ++mt)
#pragma unroll
        for (int nt = 0; nt < 8; ++nt)
#pragma unroll
            for (int q = 0; q < 4; ++q) acc[mt][nt][q] = 0.0f;

    int jj = lane >> 3;
    // A lane addr (m16k16 x4): matrices [r0-7,k0-7],[r8-15,k0-7],[r0-7,k8-15],[r8-15,k8-15]
    uint32_t aAddr = At_b + (uint32_t)(wm * 32 + (jj & 1) * 8 + (lane & 7)) * 272u
                   + (uint32_t)(jj >> 1) * 16u;
    // B lane addr (n16k16 x4): matrices [n0-7,k0-7],[n0-7,k8-15],[n8-15,k0-7],[n8-15,k8-15]
    uint32_t bAddr = W_b + (uint32_t)(wn * 64 + (jj >> 1) * 8 + (lane & 7)) * 272u
                   + (uint32_t)(jj & 1) * 16u;

#pragma unroll
    for (int kc = 0; kc < 8; ++kc) {
        uint32_t koff = (uint32_t)kc * 32u;
        uint32_t a0[4], a1[4];
        LDSM4(a0, aAddr + koff);
        LDSM4(a1, aAddr + koff + 16u * 272u);
#pragma unroll
        for (int ntt = 0; ntt < 4; ++ntt) {
            uint32_t b[4];
            LDSM4(b, bAddr + koff + (uint32_t)ntt * (16u * 272u));
            MMAH(acc[0][2 * ntt],     a0[0], a0[1], a0[2], a0[3], b[0], b[1]);
            MMAH(acc[0][2 * ntt + 1], a0[0], a0[1], a0[2], a0[3], b[2], b[3]);
            MMAH(acc[1][2 * ntt],     a1[0], a1[1], a1[2], a1[3], b[0], b[1]);
            MMAH(acc[1][2 * ntt + 1], a1[0], a1[1], a1[2], a1[3], b[2], b[3]);
        }
    }

    // epilogue: bias + silu(fp32) + partial layer3 dot (warp covers 64 cols, 32 rows)
    float p0[4] = {0, 0, 0, 0}, p1[4] = {0, 0, 0, 0};
#pragma unroll
    for (int nt = 0; nt < 8; ++nt) {
        int c0 = wn * 64 + nt * 8 + tg * 2;
        float bA = b2[c0], bB = b2[c0 + 1];
        float2 wA = *(const float2*)(w3 + c0 * 2);
        float2 wB = *(const float2*)(w3 + c0 * 2 + 2);
#pragma unroll
        for (int mt = 0; mt < 2; ++mt)
#pragma unroll
            for (int hf = 0; hf < 2; ++hf) {
                float h0 = siluf(acc[mt][nt][hf * 2] + bA);
                float h1 = siluf(acc[mt][nt][hf * 2 + 1] + bB);
                int i = mt * 2 + hf;
                p0[i] += h0 * wA.x + h1 * wB.x;
                p1[i] += h0 * wA.y + h1 * wB.y;
            }
    }
#pragma unroll
    for (int i = 0; i < 4; ++i) {
        p0[i] += __shfl_xor_sync(~0u, p0[i], 1);
        p0[i] += __shfl_xor_sync(~0u, p0[i], 2);
        p1[i] += __shfl_xor_sync(~0u, p1[i], 1);
        p1[i] += __shfl_xor_sync(~0u, p1[i], 2);
    }
    if (tg == 0) {
        float* st = wn ? st1 : st0;
#pragma unroll
        for (int i = 0; i < 4; ++i) {
            int row = wm * 32 + (i >> 1) * 16 + g + (i & 1) * 8;
            st[row * 2]     = p0[i];
            st[row * 2 + 1] = p1[i];
        }
    }
}

__global__ void __launch_bounds__(512, 1)
sde_mma_kernel(const float* __restrict__ z0, const float* __restrict__ noise,
               const float* __restrict__ dW1, const float* __restrict__ dW2,
               const float* __restrict__ db2, const float* __restrict__ dW3,
               const float* __restrict__ db3,
               const float* __restrict__ cW1, const float* __restrict__ cW2,
               const float* __restrict__ cb2, const float* __restrict__ cW3,
               const float* __restrict__ cb3, float* __restrict__ out) {
    extern __shared__ uint32_t sw[];
    float* fs   = (float*)(sw + T_FLT);
    float* zsm  = fs;            // 256
    float* b2d  = fs + 256;      // 128
    float* b2c  = fs + 384;      // 128
    float* w3d  = fs + 512;      // 256
    float* w3c  = fs + 768;      // 256
    float* su0  = fs + 1024;     // 256
    float* su1  = fs + 1280;     // 256
    float* sf0  = fs + 1536;     // 256
    float* sf1  = fs + 1792;     // 256
    float* b3s  = fs + 2048;     // 4

    int tid = threadIdx.x, lane = tid & 31;
    int h = tid >> 8;            // half: 0=diffusion, 1=cnf
    int htid = tid & 255;
    int widh = htid >> 5;        // warp within half (0..7)
    size_t row0 = (size_t)blockIdx.x * ROWS;
    uint32_t sb = smem_u32(sw);

    // W2 transposed (Wt[n][k]) single fp16, both nets
    for (int i = tid; i < HID * HID; i += 512) {
        int k = i >> 7, n = i & 127;
        ((__half*)(sw + T_WDH))[n * 136 + k] = __float2half(dW2[i]);
        ((__half*)(sw + T_WCH))[n * 136 + k] = __float2half(cW2[i]);
    }
    if (tid < 128)      b2d[tid] = db2[tid];
    else if (tid < 256) b2c[tid - 128] = cb2[tid - 128];
    if (tid < 256) w3d[tid] = dW3[tid];
    else           w3c[tid - 256] = cW3[tid - 256];
    if (tid < 2)   { b3s[tid] = db3[tid]; b3s[2 + tid] = cb3[tid]; }
    if (tid < 256) {
        float zv = z0[row0 * 2 + tid];
        zsm[tid] = zv;
        out[row0 * 2 + tid] = zv;   // traj[0]
    }

    // per-thread layer1 constants (column fixed per thread)
    int cc = (htid & 63) * 2;
    const float* W1g = h ? cW1 : dW1;
    float w1aa = W1g[cc], w1ab = W1g[cc + 1];
    float w1ba = W1g[HID + cc], w1bb = W1g[HID + cc + 1];
    const float* prebase = (h ? g_cctx : g_dctx) + row0 * HID + cc;
    const float* tvg = h ? g_tvc : g_tvd;
    uint32_t* At = sw + (h ? T_AC : T_AD);
    uint32_t At_b = sb + (h ? T_AC : T_AD) * 4u;
    uint32_t W_b  = sb + (h ? T_WCH : T_WDH) * 4u;
    const float* b2 = h ? b2c : b2d;
    const float* w3 = h ? w3c : w3d;
    float* st0 = h ? sf0 : su0;
    float* st1 = h ? sf1 : su1;
    int aw = (cc >> 1);
    const uint32_t HALFC = 0x38003800u;   // (0.5, 0.5) f16x2
    __syncthreads();

    for (int s = 0; s < NSTEPS; ++s) {
        float2 tvv = *(const float2*)(tvg + s * HID + cc);
        float dt = g_dt[s], gsc = g_gs[s];
        float xi = 0.0f;
        if (tid < 256) xi = noise[(size_t)s * ((size_t)NPTS * 2) + row0 * 2 + tid];

        // layer1 (f16x2 tanh silu) -> fp16 A tile
        {
            int r = htid >> 6;   // 0..3, stride 4 -> 32 rows each
#pragma unroll 4
            for (int k = 0; k < 32; ++k, r += 4) {
                float2 pv = *(const float2*)(prebase + r * HID);
                float za = zsm[2 * r], zb = zsm[2 * r + 1];
                float x0 = pv.x + tvv.x + za * w1aa + zb * w1ba;
                float x1 = pv.y + tvv.y + za * w1ab + zb * w1bb;
                uint32_t xp, xh, t, u, hp;
                asm("cvt.rn.f16x2.f32 %0,%1,%2;" : "=r"(xp) : "f"(x1), "f"(x0));
                asm("mul.rn.f16x2 %0,%1,%2;" : "=r"(xh) : "r"(xp), "r"(HALFC));
                asm("tanh.approx.f16x2 %0,%1;" : "=r"(t) : "r"(xh));
                asm("fma.rn.f16x2 %0,%1,%2,%3;" : "=r"(u) : "r"(t), "r"(HALFC), "r"(HALFC));
                asm("mul.rn.f16x2 %0,%1,%2;" : "=r"(hp) : "r"(xp), "r"(u));
                At[r * LDAW + aw] = hp;
            }
        }
        asm volatile("bar.sync %0, 256;" :: "r"(1 + h) : "memory");

        net_pass(At_b, W_b, b2, w3, st0, st1, widh, lane);
        __syncthreads();

        if (tid < 256) {   // SDE update: 256 threads = 128 rows x 2 dims
            float au = su0[tid] + su1[tid] + b3s[tid & 1];
            float af = sf0[tid] + sf1[tid] + b3s[2 + (tid & 1)];
            size_t gi = row0 * 2 + tid;
            float zn = zsm[tid] + (af + au) * dt + xi * gsc;
            out[OUT_US + (size_t)s * ((size_t)NPTS * 2) + gi] = au;
            out[(size_t)(s + 1) * ((size_t)NPTS * 2) + gi]    = zn;
            zsm[tid] = zn;
        }
        __syncthreads();   // zsm visible, stages free for next step
    }
}

extern "C" void kernel_launch(void* const* d_in, const int* in_sizes, int n_in,
                              void* d_out, int out_size) {
    (void)in_sizes; (void)n_in; (void)out_size;
    const float* z0    = (const float*)d_in[0];
    const float* pctx  = (const float*)d_in[1];
    const float* cctx  = (const float*)d_in[2];
    const float* times = (const float*)d_in[3];
    const float* noise = (const float*)d_in[4];
    const float* freqs = (const float*)d_in[5];
    const float* dW1   = (const float*)d_in[6];
    const float* db1   = (const float*)d_in[7];
    const float* dW2   = (const float*)d_in[8];
    const float* db2   = (const float*)d_in[9];
    const float* dW3   = (const float*)d_in[10];
    const float* db3   = (const float*)d_in[11];
    const float* cW1   = (const float*)d_in[12];
    const float* cb1   = (const float*)d_in[13];
    const float* cW2   = (const float*)d_in[14];
    const float* cb2   = (const float*)d_in[15];
    const float* cW3   = (const float*)d_in[16];
    const float* cb3   = (const float*)d_in[17];
    const float* logd  = (const float*)d_in[18];
    float* out = (float*)d_out;

    const int CTX_SMEM = (HID * HID + 64 * AS_LD) * (int)sizeof(float);
    static int done = 0;
    if (!done) {
        cudaFuncSetAttribute(ctx_kernel, cudaFuncAttributeMaxDynamicSharedMemorySize, CTX_SMEM);
        cudaFuncSetAttribute(sde_mma_kernel, cudaFuncAttributeMaxDynamicSharedMemorySize, SDE_SMEM);
        done = 1;
    }
    step_const_kernel<<<NSTEPS, 128>>>(times, freqs, dW1, cW1, logd, out);
    ctx_kernel<<<2 * (NPTS / 64), 256, CTX_SMEM>>>(pctx, cctx, dW1, db1, cW1, cb1);
    sde_mma_kernel<<<NPTS / ROWS, 512, SDE_SMEM>>>(z0, noise, dW1, dW2, db2, dW3, db3,
                                                   cW1, cW2, cb2, cW3, cb3, out);
}

// round 16
// speedup vs baseline: 1.9580x; 1.1328x over previous
#include <cuda_runtime.h>
#include <cuda_bf16.h>
#include <cuda_fp16.h>
#include <math.h>
#include <stdint.h>

#define NPTS 262144
#define HID 128
#define NSTEPS 50
#define AS_LD 129
#define ROWS 64           // rows per CTA (2 CTAs/SM)
#define LDAW 68           // uint32 words per tile row (136 halves)

#define OUT_US    ((size_t)(NSTEPS + 1) * NPTS * 2)
#define OUT_TIMES (OUT_US + (size_t)NSTEPS * NPTS * 2)

__device__ float g_dctx[NPTS * HID];
__device__ float g_cctx[NPTS * HID];
__device__ float g_tvd[NSTEPS * HID];
__device__ float g_tvc[NSTEPS * HID];
__device__ float g_dt[NSTEPS];
__device__ float g_gs[NSTEPS];

// fast silu (fp32): 1 MUFU + 2 FMA
__device__ __forceinline__ float siluf(float x) {
    float t;
    asm("tanh.approx.f32 %0, %1;" : "=f"(t) : "f"(x * 0.5f));
    return x * fmaf(0.5f, t, 0.5f);
}

__device__ __forceinline__ uint32_t smem_u32(const void* p) {
    uint32_t a;
    asm("{ .reg .u64 t; cvta.to.shared.u64 t, %1; cvt.u32.u64 %0, t; }" : "=r"(a) : "l"(p));
    return a;
}

#define MMAH(d, a0, a1, a2, a3, b0, b1) asm volatile( \
    "mma.sync.aligned.m16n8k16.row.col.f32.f16.f16.f32 " \
    "{%0,%1,%2,%3},{%4,%5,%6,%7},{%8,%9},{%0,%1,%2,%3};" \
    : "+f"((d)[0]), "+f"((d)[1]), "+f"((d)[2]), "+f"((d)[3]) \
    : "r"(a0), "r"(a1), "r"(a2), "r"(a3), "r"(b0), "r"(b1))

#define LDSM4(r, addr) asm volatile( \
    "ldmatrix.sync.aligned.m8n8.x4.shared.b16 {%0,%1,%2,%3}, [%4];" \
    : "=r"((r)[0]), "=r"((r)[1]), "=r"((r)[2]), "=r"((r)[3]) : "r"(addr))

// ---------- FFMA2 GEMM (ctx precompute, known-good) ----------
__device__ __forceinline__ void gemm_core(const float* __restrict__ As,
                                          const float* __restrict__ Ws,
                                          int r0, int c0, unsigned long long (&acc)[4][4]) {
#pragma unroll
    for (int i = 0; i < 4; ++i)
#pragma unroll
        for (int j = 0; j < 4; ++j) acc[i][j] = 0ull;
#pragma unroll 4
    for (int k = 0; k < HID; ++k) {
        unsigned long long h[4];
#pragma unroll
        for (int i = 0; i < 4; ++i) {
            unsigned v = __float_as_uint(As[(r0 + i) * AS_LD + k]);
            asm("mov.b64 %0, {%1, %1};" : "=l"(h[i]) : "r"(v));
        }
        const float* wr = Ws + k * HID + c0;
        ulonglong2 wa = *(const ulonglong2*)(wr);
        ulonglong2 wb = *(const ulonglong2*)(wr + 4);
#pragma unroll
        for (int i = 0; i < 4; ++i) {
            asm("fma.rn.f32x2 %0, %1, %2, %0;" : "+l"(acc[i][0]) : "l"(h[i]), "l"(wa.x));
            asm("fma.rn.f32x2 %0, %1, %2, %0;" : "+l"(acc[i][1]) : "l"(h[i]), "l"(wa.y));
            asm("fma.rn.f32x2 %0, %1, %2, %0;" : "+l"(acc[i][2]) : "l"(h[i]), "l"(wb.x));
            asm("fma.rn.f32x2 %0, %1, %2, %0;" : "+l"(acc[i][3]) : "l"(h[i]), "l"(wb.y));
        }
    }
}

// both ctx GEMMs in one launch: which = blockIdx.x >> 12
__global__ void __launch_bounds__(256, 2)
ctx_kernel(const float* __restrict__ Xp, const float* __restrict__ Xc,
           const float* __restrict__ dW1, const float* __restrict__ db1,
           const float* __restrict__ cW1, const float* __restrict__ cb1) {
    extern __shared__ float sm[];
    float* Ws = sm;
    float* Xs = sm + HID * HID;
    int which = blockIdx.x >> 12;
    const float* X  = which ? Xc : Xp;
    const float* W1 = which ? cW1 : dW1;
    const float* b1 = which ? cb1 : db1;
    float* out = which ? g_cctx : g_dctx;
    int tid = threadIdx.x;
    size_t row0 = (size_t)(blockIdx.x & 4095) * 64;
    for (int i = tid; i < HID * HID; i += 256) Ws[i] = W1[2 * HID + i];
#pragma unroll 4
    for (int i = tid; i < 64 * HID; i += 256) {
        int r = i >> 7, c = i & 127;
        Xs[r * AS_LD + c] = X[(row0 + r) * HID + c];
    }
    __syncthreads();
    int r0 = (tid >> 4) * 4, c0 = (tid & 15) * 8;
    unsigned long long acc[4][4];
    gemm_core(Xs, Ws, r0, c0, acc);
#pragma unroll
    for (int i = 0; i < 4; ++i) {
        size_t base = (row0 + r0 + i) * HID + c0;
#pragma unroll
        for (int j = 0; j < 4; ++j) {
            unsigned lo, hi;
            asm("mov.b64 {%0, %1}, %2;" : "=r"(lo), "=r"(hi) : "l"(acc[i][j]));
            float2 v;
            v.x = __uint_as_float(lo) + b1[c0 + 2 * j];
            v.y = __uint_as_float(hi) + b1[c0 + 2 * j + 1];
            *(float2*)&out[base + 2 * j] = v;
        }
    }
}

__global__ void __launch_bounds__(128)
step_const_kernel(const float* __restrict__ times, const float* __restrict__ freqs,
                  const float* __restrict__ dW1, const float* __restrict__ cW1,
                  const float* __restrict__ logd, float* __restrict__ out) {
    int s = blockIdx.x, t = threadIdx.x;
    __shared__ float temb[32];
    float t_i = times[s];
    if (t < 32) {
        float a = 6.28318530717958647692f * t_i * freqs[t & 15];
        temb[t] = (t < 16) ? sinf(a) : cosf(a);
    }
    __syncthreads();
    float sd = 0.0f, sc = 0.0f;
#pragma unroll
    for (int k = 0; k < 32; ++k) {
        sd += temb[k] * dW1[(130 + k) * HID + t];
        sc += temb[k] * cW1[(130 + k) * HID + t];
    }
    g_tvd[s * HID + t] = sd;
    g_tvc[s * HID + t] = sc;
    if (t == 0) {
        float dt = times[s + 1] - t_i;
        g_dt[s] = dt;
        g_gs[s] = log1pf(expf(logd[0])) * (1.0f - t_i) * sqrtf(fmaxf(dt, 1e-12f));
    }
    if (s == 0 && t < NSTEPS + 1) out[OUT_TIMES + t] = times[t];
}

// ---------- main HMMA SDE kernel: 256 threads, 2 CTAs/SM ----------
// word offsets; A tile 64x68 = 4352 words, W tile 128x68 = 8704 words
#define T_AD  0
#define T_AC  4352
#define T_WDH 8704
#define T_WCH 17408
#define T_FLT 26112
#define SDE_WORDS (T_FLT + 1412)
#define SDE_SMEM (SDE_WORDS * 4)   // 110096 B -> 2 CTAs = 220KB/SM

// GEMM + fused epilogue for one net; 4 warps (widh 0..3), warp tile 32r x 64c
__device__ __forceinline__ void net_pass(uint32_t At_b, uint32_t W_b,
                                         const float* __restrict__ b2,
                                         const float* __restrict__ w3,
                                         float* __restrict__ st0, float* __restrict__ st1,
                                         int widh, int lane) {
    int wm = widh & 1, wn = widh >> 1, g = lane >> 2, tg = lane & 3;
    float acc[2][8][4];
#pragma unroll
    for (int mt = 0; mt < 2; ++mt)
#pragma unroll
        for (int nt = 0; nt < 8; ++nt)
#pragma unroll
            for (int q = 0; q < 4; ++q) acc[mt][nt][q] = 0.0f;

    int jj = lane >> 3;
    uint32_t aAddr = At_b + (uint32_t)(wm * 32 + (jj & 1) * 8 + (lane & 7)) * 272u
                   + (uint32_t)(jj >> 1) * 16u;
    uint32_t bAddr = W_b + (uint32_t)(wn * 64 + (jj >> 1) * 8 + (lane & 7)) * 272u
                   + (uint32_t)(jj & 1) * 16u;

#pragma unroll
    for (int kc = 0; kc < 8; ++kc) {
        uint32_t koff = (uint32_t)kc * 32u;
        uint32_t a0[4], a1[4];
        LDSM4(a0, aAddr + koff);
        LDSM4(a1, aAddr + koff + 16u * 272u);
#pragma unroll
        for (int ntt = 0; ntt < 4; ++ntt) {
            uint32_t b[4];
            LDSM4(b, bAddr + koff + (uint32_t)ntt * (16u * 272u));
            MMAH(acc[0][2 * ntt],     a0[0], a0[1], a0[2], a0[3], b[0], b[1]);
            MMAH(acc[0][2 * ntt + 1], a0[0], a0[1], a0[2], a0[3], b[2], b[3]);
            MMAH(acc[1][2 * ntt],     a1[0], a1[1], a1[2], a1[3], b[0], b[1]);
            MMAH(acc[1][2 * ntt + 1], a1[0], a1[1], a1[2], a1[3], b[2], b[3]);
        }
    }

    // epilogue: bias + silu(fp32) + partial layer3 dot (warp covers 64 cols, 32 rows)
    float p0[4] = {0, 0, 0, 0}, p1[4] = {0, 0, 0, 0};
#pragma unroll
    for (int nt = 0; nt < 8; ++nt) {
        int c0 = wn * 64 + nt * 8 + tg * 2;
        float bA = b2[c0], bB = b2[c0 + 1];
        float2 wA = *(const float2*)(w3 + c0 * 2);
        float2 wB = *(const float2*)(w3 + c0 * 2 + 2);
#pragma unroll
        for (int mt = 0; mt < 2; ++mt)
#pragma unroll
            for (int hf = 0; hf < 2; ++hf) {
                float h0 = siluf(acc[mt][nt][hf * 2] + bA);
                float h1 = siluf(acc[mt][nt][hf * 2 + 1] + bB);
                int i = mt * 2 + hf;
                p0[i] += h0 * wA.x + h1 * wB.x;
                p1[i] += h0 * wA.y + h1 * wB.y;
            }
    }
#pragma unroll
    for (int i = 0; i < 4; ++i) {
        p0[i] += __shfl_xor_sync(~0u, p0[i], 1);
        p0[i] += __shfl_xor_sync(~0u, p0[i], 2);
        p1[i] += __shfl_xor_sync(~0u, p1[i], 1);
        p1[i] += __shfl_xor_sync(~0u, p1[i], 2);
    }
    if (tg == 0) {
        float* st = wn ? st1 : st0;
#pragma unroll
        for (int i = 0; i < 4; ++i) {
            int row = wm * 32 + (i >> 1) * 16 + g + (i & 1) * 8;
            st[row * 2]     = p0[i];
            st[row * 2 + 1] = p1[i];
        }
    }
}

__global__ void __launch_bounds__(256, 2)
sde_mma_kernel(const float* __restrict__ z0, const float* __restrict__ noise,
               const float* __restrict__ dW1, const float* __restrict__ dW2,
               const float* __restrict__ db2, const float* __restrict__ dW3,
               const float* __restrict__ db3,
               const float* __restrict__ cW1, const float* __restrict__ cW2,
               const float* __restrict__ cb2, const float* __restrict__ cW3,
               const float* __restrict__ cb3, float* __restrict__ out) {
    extern __shared__ uint32_t sw[];
    float* fs   = (float*)(sw + T_FLT);
    float* zsm  = fs;            // 128
    float* b2d  = fs + 128;      // 128
    float* b2c  = fs + 256;      // 128
    float* w3d  = fs + 384;      // 256
    float* w3c  = fs + 640;      // 256
    float* su0  = fs + 896;      // 128
    float* su1  = fs + 1024;     // 128
    float* sf0  = fs + 1152;     // 128
    float* sf1  = fs + 1280;     // 128
    float* b3s  = fs + 1408;     // 4

    int tid = threadIdx.x, lane = tid & 31;
    int h = tid >> 7;            // half: 0=diffusion, 1=cnf (4 warps each)
    int htid = tid & 127;
    int widh = htid >> 5;        // warp within half (0..3)
    size_t row0 = (size_t)blockIdx.x * ROWS;
    uint32_t sb = smem_u32(sw);

    // W2 transposed (Wt[n][k]) single fp16, both nets
    for (int i = tid; i < HID * HID; i += 256) {
        int k = i >> 7, n = i & 127;
        ((__half*)(sw + T_WDH))[n * 136 + k] = __float2half(dW2[i]);
        ((__half*)(sw + T_WCH))[n * 136 + k] = __float2half(cW2[i]);
    }
    if (tid < 128)      b2d[tid] = db2[tid];
    else                b2c[tid - 128] = cb2[tid - 128];
    // w3: 256 values per net
    w3d[tid] = dW3[tid];
    w3c[tid] = cW3[tid];
    if (tid < 2)   { b3s[tid] = db3[tid]; b3s[2 + tid] = cb3[tid]; }
    if (tid < 128) {
        float zv = z0[row0 * 2 + tid];
        zsm[tid] = zv;
        out[row0 * 2 + tid] = zv;   // traj[0]
    }

    // per-thread layer1 constants (column fixed per thread)
    int cc = (htid & 63) * 2;
    int r0l = htid >> 6;             // 0..1, stride 2 -> 32 rows each
    const float* W1g = h ? cW1 : dW1;
    float w1aa = W1g[cc], w1ab = W1g[cc + 1];
    float w1ba = W1g[HID + cc], w1bb = W1g[HID + cc + 1];
    const float* prebase = (h ? g_cctx : g_dctx) + row0 * HID + cc;
    const float* tvg = h ? g_tvc : g_tvd;
    uint32_t* At = sw + (h ? T_AC : T_AD);
    uint32_t At_b = sb + (h ? T_AC : T_AD) * 4u;
    uint32_t W_b  = sb + (h ? T_WCH : T_WDH) * 4u;
    const float* b2 = h ? b2c : b2d;
    const float* w3 = h ? w3c : w3d;
    float* st0 = h ? sf0 : su0;
    float* st1 = h ? sf1 : su1;
    int aw = (cc >> 1);
    const uint32_t HALFC = 0x38003800u;   // (0.5, 0.5) f16x2
    __syncthreads();

    for (int s = 0; s < NSTEPS; ++s) {
        float2 tvv = *(const float2*)(tvg + s * HID + cc);
        float dt = g_dt[s], gsc = g_gs[s];
        float xi = 0.0f;
        if (tid < 128) xi = noise[(size_t)s * ((size_t)NPTS * 2) + row0 * 2 + tid];

        // layer1 (f16x2 tanh silu) -> fp16 A tile (64 rows)
        {
            int r = r0l;   // 0..1, stride 2 -> 32 rows per thread
#pragma unroll 4
            for (int k = 0; k < 32; ++k, r += 2) {
                float2 pv = *(const float2*)(prebase + r * HID);
                float za = zsm[2 * r], zb = zsm[2 * r + 1];
                float x0 = pv.x + tvv.x + za * w1aa + zb * w1ba;
                float x1 = pv.y + tvv.y + za * w1ab + zb * w1bb;
                uint32_t xp, xh, t, u, hp;
                asm("cvt.rn.f16x2.f32 %0,%1,%2;" : "=r"(xp) : "f"(x1), "f"(x0));
                asm("mul.rn.f16x2 %0,%1,%2;" : "=r"(xh) : "r"(xp), "r"(HALFC));
                asm("tanh.approx.f16x2 %0,%1;" : "=r"(t) : "r"(xh));
                asm("fma.rn.f16x2 %0,%1,%2,%3;" : "=r"(u) : "r"(t), "r"(HALFC), "r"(HALFC));
                asm("mul.rn.f16x2 %0,%1,%2;" : "=r"(hp) : "r"(xp), "r"(u));
                At[r * LDAW + aw] = hp;
            }
        }
        asm volatile("bar.sync %0, 128;" :: "r"(1 + h) : "memory");

        net_pass(At_b, W_b, b2, w3, st0, st1, widh, lane);
        __syncthreads();

        if (tid < 128) {   // SDE update: 128 threads = 64 rows x 2 dims
            float au = su0[tid] + su1[tid] + b3s[tid & 1];
            float af = sf0[tid] + sf1[tid] + b3s[2 + (tid & 1)];
            size_t gi = row0 * 2 + tid;
            float zn = zsm[tid] + (af + au) * dt + xi * gsc;
            out[OUT_US + (size_t)s * ((size_t)NPTS * 2) + gi] = au;
            out[(size_t)(s + 1) * ((size_t)NPTS * 2) + gi]    = zn;
            zsm[tid] = zn;
        }
        __syncthreads();   // zsm visible, stages free for next step
    }
}

extern "C" void kernel_launch(void* const* d_in, const int* in_sizes, int n_in,
                              void* d_out, int out_size) {
    (void)in_sizes; (void)n_in; (void)out_size;
    const float* z0    = (const float*)d_in[0];
    const float* pctx  = (const float*)d_in[1];
    const float* cctx  = (const float*)d_in[2];
    const float* times = (const float*)d_in[3];
    const float* noise = (const float*)d_in[4];
    const float* freqs = (const float*)d_in[5];
    const float* dW1   = (const float*)d_in[6];
    const float* db1   = (const float*)d_in[7];
    const float* dW2   = (const float*)d_in[8];
    const float* db2   = (const float*)d_in[9];
    const float* dW3   = (const float*)d_in[10];
    const float* db3   = (const float*)d_in[11];
    const float* cW1   = (const float*)d_in[12];
    const float* cb1   = (const float*)d_in[13];
    const float* cW2   = (const float*)d_in[14];
    const float* cb2   = (const float*)d_in[15];
    const float* cW3   = (const float*)d_in[16];
    const float* cb3   = (const float*)d_in[17];
    const float* logd  = (const float*)d_in[18];
    float* out = (float*)d_out;

    const int CTX_SMEM = (HID * HID + 64 * AS_LD) * (int)sizeof(float);
    static int done = 0;
    if (!done) {
        cudaFuncSetAttribute(ctx_kernel, cudaFuncAttributeMaxDynamicSharedMemorySize, CTX_SMEM);
        cudaFuncSetAttribute(sde_mma_kernel, cudaFuncAttributeMaxDynamicSharedMemorySize, SDE_SMEM);
        done = 1;
    }
    step_const_kernel<<<NSTEPS, 128>>>(times, freqs, dW1, cW1, logd, out);
    ctx_kernel<<<2 * (NPTS / 64), 256, CTX_SMEM>>>(pctx, cctx, dW1, db1, cW1, cb1);
    sde_mma_kernel<<<NPTS / ROWS, 256, SDE_SMEM>>>(z0, noise, dW1, dW2, db2, dW3, db3,
                                                   cW1, cW2, cb2, cW3, cb3, out);
}